// round 6
// baseline (speedup 1.0000x reference)
#include <cuda_runtime.h>
#include <math.h>
#include <stdint.h>

// FlashAttention fwd, causal, fp32 I/O, tf32 mma.sync, sm_103.
// B=1, S=4096, H=16, D=64. Layout [s,h,d]: d contiguous, s stride 1024.
//
// CTA = (head, 64 q rows), 4 warps x 16 rows, 12 warps/SM target.
// BN=32 kv tiles: cp.async double-buffered raw fp32, then an in-smem pass
// rna-rounds K in place and rounds+transposes V into Vt (conflict-free MMA2).

constexpr int S_LEN = 4096;
constexpr int H     = 16;
constexpr int Dh    = 64;
constexpr int BM    = 64;
constexpr int BN    = 32;
constexpr int NT    = 128;
constexpr int PAD   = 68;   // K / Ps row pitch (floats): (4g+tg) conflict-free
constexpr int PADT  = 36;   // Vt row pitch: (4g+tg) conflict-free

// smem float offsets
constexpr int KR_OFF = 0;                       // 2 x 32x68
constexpr int VR_OFF = 2 * BN * PAD;            // 2 x 32x68 (raw V)
constexpr int VT_OFF = 4 * BN * PAD;            // 64x36 (rounded V^T)
constexpr int PS_OFF = VT_OFF + Dh * PADT;      // 64x68 (Q staging / P)
constexpr int SMEM_F = PS_OFF + BM * PAD;
constexpr int SMEM_BYTES = SMEM_F * 4;          // 61440 B -> 3 CTAs/SM

__device__ __forceinline__ uint32_t f2tf32(float f) {
    uint32_t r;
    asm("cvt.rna.tf32.f32 %0, %1;" : "=r"(r) : "f"(f));
    return r;
}
__device__ __forceinline__ float ex2(float x) {
    float y;
    asm("ex2.approx.f32 %0, %1;" : "=f"(y) : "f"(x));
    return y;
}
__device__ __forceinline__ void mma8(float* d, const uint32_t* a, const uint32_t* b) {
    asm volatile(
        "mma.sync.aligned.m16n8k8.row.col.f32.tf32.tf32.f32 "
        "{%0,%1,%2,%3}, {%4,%5,%6,%7}, {%8,%9}, {%0,%1,%2,%3};"
        : "+f"(d[0]), "+f"(d[1]), "+f"(d[2]), "+f"(d[3])
        : "r"(a[0]), "r"(a[1]), "r"(a[2]), "r"(a[3]), "r"(b[0]), "r"(b[1]));
}
__device__ __forceinline__ void cpa16(uint32_t dst, const float* src) {
    asm volatile("cp.async.cg.shared.global [%0], [%1], 16;"
                 :: "r"(dst), "l"(src) : "memory");
}

// one 32x64 K tile + V tile (raw) -> smem; 4+4 16B chunks per thread
__device__ __forceinline__ void issue_tile(uint32_t kdst, uint32_t vdst,
                                           const float* kbase, const float* vbase,
                                           int k0, int t) {
    #pragma unroll
    for (int i = 0; i < 4; i++) {
        int idx = t + i * NT;           // 0..511
        int row = idx >> 4, c4 = idx & 15;
        size_t go = (size_t)(k0 + row) * (H * Dh) + (size_t)c4 * 4;
        uint32_t so = (uint32_t)(row * (PAD * 4) + c4 * 16);
        cpa16(kdst + so, kbase + go);
        cpa16(vdst + so, vbase + go);
    }
    asm volatile("cp.async.commit_group;" ::: "memory");
}

__global__ void __launch_bounds__(NT, 3)
fa_mma_kernel(const float* __restrict__ q, const float* __restrict__ k,
              const float* __restrict__ v, const int* __restrict__ causal_p,
              float* __restrict__ out)
{
    extern __shared__ float sm[];
    uint32_t smb;
    asm("{ .reg .u64 t; cvta.to.shared.u64 t, %1; cvt.u32.u64 %0, t; }"
        : "=r"(smb) : "l"(sm));
    float* Vt = sm + VT_OFF;
    float* Ps = sm + PS_OFF;

    const int t    = threadIdx.x;
    const int lane = t & 31;
    const int g    = lane >> 2;
    const int tg   = lane & 3;
    const int h    = blockIdx.x;
    const int qb   = (int)gridDim.y - 1 - (int)blockIdx.y;  // heavy tiles first
    const int causal = *causal_p;
    const int wb   = (t >> 5) * 16;     // warp's 16-row base in CTA tile
    const float c  = 0.125f * 1.44269504088896340736f;      // D^-0.5 * log2(e)

    const float* kbase = k + (size_t)h * Dh;
    const float* vbase = v + (size_t)h * Dh;
    const int ktiles = causal ? 2 * (qb + 1) : (S_LEN / BN);

    // ---- prefetch kv tile 0 into buffer 0
    issue_tile(smb + KR_OFF * 4, smb + VR_OFF * 4, kbase, vbase, 0, t);

    // ---- stage Q (scale folded, rna tf32) into Ps; lift fragments
    #pragma unroll
    for (int i = 0; i < 8; i++) {
        int idx = t + i * NT, row = idx >> 4, c4 = idx & 15;
        float4 f = ((const float4*)(q + (size_t)(qb * BM + row) * (H * Dh) + h * Dh))[c4];
        uint32_t* d = (uint32_t*)(Ps + row * PAD + c4 * 4);
        d[0] = f2tf32(f.x * c); d[1] = f2tf32(f.y * c);
        d[2] = f2tf32(f.z * c); d[3] = f2tf32(f.w * c);
    }
    __syncthreads();

    uint32_t qa[8][4];                  // [ktile][frag], warp-private rows
    {
        int r0 = wb + g;
        #pragma unroll
        for (int kt = 0; kt < 8; kt++) {
            qa[kt][0] = __float_as_uint(Ps[r0 * PAD + kt * 8 + tg]);
            qa[kt][1] = __float_as_uint(Ps[(r0 + 8) * PAD + kt * 8 + tg]);
            qa[kt][2] = __float_as_uint(Ps[r0 * PAD + kt * 8 + tg + 4]);
            qa[kt][3] = __float_as_uint(Ps[(r0 + 8) * PAD + kt * 8 + tg + 4]);
        }
    }

    float o[8][4];
    #pragma unroll
    for (int nt = 0; nt < 8; nt++)
        #pragma unroll
        for (int e = 0; e < 4; e++) o[nt][e] = 0.0f;
    float mrow[2] = {-INFINITY, -INFINITY};
    float lrow[2] = {0.0f, 0.0f};

    for (int kb = 0; kb < ktiles; kb++) {
        const int k0 = kb * BN;
        const int cur = kb & 1;
        float* Kr = sm + KR_OFF + cur * (BN * PAD);
        float* Vr = sm + VR_OFF + cur * (BN * PAD);

        __syncthreads();   // prev iter fully consumed (Kr/Vt/Ps reads done)
        if (kb + 1 < ktiles)
            issue_tile(smb + (KR_OFF + (cur ^ 1) * BN * PAD) * 4,
                       smb + (VR_OFF + (cur ^ 1) * BN * PAD) * 4,
                       kbase, vbase, k0 + BN, t);
        else
            asm volatile("cp.async.commit_group;" ::: "memory");
        asm volatile("cp.async.wait_group 1;" ::: "memory");
        __syncthreads();   // raw tile kb visible

        // ---- rounding pass: K rna in place; V rna + transpose -> Vt
        #pragma unroll
        for (int i = 0; i < 4; i++) {
            int idx = t + i * NT;          // 0..511
            int row = idx & 31, cc = idx >> 5;   // row=kv, cc=0..15 (4-col chunk)
            float4 fk = *(float4*)(Kr + row * PAD + cc * 4);
            uint32_t* dk = (uint32_t*)(Kr + row * PAD + cc * 4);
            dk[0] = f2tf32(fk.x); dk[1] = f2tf32(fk.y);
            dk[2] = f2tf32(fk.z); dk[3] = f2tf32(fk.w);
            float4 fv = *(float4*)(Vr + row * PAD + cc * 4);
            uint32_t* vt = (uint32_t*)(Vt + (cc * 4) * PADT + row);
            vt[0 * PADT] = f2tf32(fv.x);
            vt[1 * PADT] = f2tf32(fv.y);
            vt[2 * PADT] = f2tf32(fv.z);
            vt[3 * PADT] = f2tf32(fv.w);
        }
        __syncthreads();   // rounded K / Vt visible

        // ---- MMA1: S[16 x 32] = Q @ K^T
        float s[4][4];
        #pragma unroll
        for (int nt = 0; nt < 4; nt++)
            #pragma unroll
            for (int e = 0; e < 4; e++) s[nt][e] = 0.0f;
        #pragma unroll
        for (int kt = 0; kt < 8; kt++) {
            #pragma unroll
            for (int nt = 0; nt < 4; nt++) {
                uint32_t b[2];
                b[0] = *(const uint32_t*)(Kr + (nt * 8 + g) * PAD + kt * 8 + tg);
                b[1] = *(const uint32_t*)(Kr + (nt * 8 + g) * PAD + kt * 8 + tg + 4);
                mma8(s[nt], qa[kt], b);
            }
        }

        // ---- causal mask (last two tiles of each CTA touch the diagonal)
        if (causal && kb >= 2 * qb) {
            int r0 = qb * BM + wb + g;
            #pragma unroll
            for (int nt = 0; nt < 4; nt++) {
                int col = k0 + nt * 8 + 2 * tg;
                if (col     > r0)     s[nt][0] = -INFINITY;
                if (col + 1 > r0)     s[nt][1] = -INFINITY;
                if (col     > r0 + 8) s[nt][2] = -INFINITY;
                if (col + 1 > r0 + 8) s[nt][3] = -INFINITY;
            }
        }

        // ---- online softmax: 2 rows per thread (g, g+8); quad owns a row
        #pragma unroll
        for (int hi = 0; hi < 2; hi++) {
            float tm = -INFINITY;
            #pragma unroll
            for (int nt = 0; nt < 4; nt++)
                tm = fmaxf(tm, fmaxf(s[nt][hi * 2], s[nt][hi * 2 + 1]));
            tm = fmaxf(tm, __shfl_xor_sync(0xffffffffu, tm, 1));
            tm = fmaxf(tm, __shfl_xor_sync(0xffffffffu, tm, 2));
            float nm   = fmaxf(mrow[hi], tm);
            float corr = ex2(mrow[hi] - nm);       // first tile: -inf -> 0
            mrow[hi] = nm;
            float ls = 0.0f;
            #pragma unroll
            for (int nt = 0; nt < 4; nt++) {
                float e0 = ex2(s[nt][hi * 2]     - nm);
                float e1 = ex2(s[nt][hi * 2 + 1] - nm);
                s[nt][hi * 2] = e0; s[nt][hi * 2 + 1] = e1;
                ls += e0 + e1;
            }
            // rescale o accumulators for this row exactly once
            #pragma unroll
            for (int d = 0; d < 8; d++) {
                o[d][hi * 2]     *= corr;
                o[d][hi * 2 + 1] *= corr;
            }
            lrow[hi] = lrow[hi] * corr + ls;
        }

        // ---- P (rna tf32) -> Ps; rows are warp-private
        {
            int r0 = wb + g;
            #pragma unroll
            for (int nt = 0; nt < 4; nt++) {
                uint32_t* d0 = (uint32_t*)(Ps + r0 * PAD + nt * 8 + 2 * tg);
                d0[0] = f2tf32(s[nt][0]); d0[1] = f2tf32(s[nt][1]);
                uint32_t* d1 = (uint32_t*)(Ps + (r0 + 8) * PAD + nt * 8 + 2 * tg);
                d1[0] = f2tf32(s[nt][2]); d1[1] = f2tf32(s[nt][3]);
            }
        }
        __syncwarp();

        // ---- MMA2: O += P[16x32] @ V[32x64]   (4 k-steps)
        #pragma unroll
        for (int kt = 0; kt < 4; kt++) {
            uint32_t pa[4];
            int r0 = wb + g;
            pa[0] = __float_as_uint(Ps[r0 * PAD + kt * 8 + tg]);
            pa[1] = __float_as_uint(Ps[(r0 + 8) * PAD + kt * 8 + tg]);
            pa[2] = __float_as_uint(Ps[r0 * PAD + kt * 8 + tg + 4]);
            pa[3] = __float_as_uint(Ps[(r0 + 8) * PAD + kt * 8 + tg + 4]);
            #pragma unroll
            for (int nt = 0; nt < 8; nt++) {
                uint32_t b[2];
                b[0] = *(const uint32_t*)(Vt + (nt * 8 + g) * PADT + kt * 8 + tg);
                b[1] = *(const uint32_t*)(Vt + (nt * 8 + g) * PADT + kt * 8 + tg + 4);
                mma8(o[nt], pa, b);
            }
        }
    }

    // ---- finalize: row-sum across quad, normalize, store
    #pragma unroll
    for (int hi = 0; hi < 2; hi++) {
        lrow[hi] += __shfl_xor_sync(0xffffffffu, lrow[hi], 1);
        lrow[hi] += __shfl_xor_sync(0xffffffffu, lrow[hi], 2);
        const float inv = 1.0f / lrow[hi];
        const int rg = qb * BM + wb + g + hi * 8;
        float* op = out + (size_t)rg * (H * Dh) + (size_t)h * Dh;
        #pragma unroll
        for (int nt = 0; nt < 8; nt++) {
            float2 f2;
            f2.x = o[nt][hi * 2]     * inv;
            f2.y = o[nt][hi * 2 + 1] * inv;
            *(float2*)(op + nt * 8 + 2 * tg) = f2;
        }
    }
}

extern "C" void kernel_launch(void* const* d_in, const int* in_sizes, int n_in,
                              void* d_out, int out_size)
{
    const float* q = (const float*)d_in[0];
    const float* k = (const float*)d_in[1];
    const float* v = (const float*)d_in[2];
    const int* causal = (const int*)d_in[3];
    float* out = (float*)d_out;

    cudaFuncSetAttribute(fa_mma_kernel,
                         cudaFuncAttributeMaxDynamicSharedMemorySize, SMEM_BYTES);
    dim3 grid(H, S_LEN / BM);   // (16, 64) = 1024 CTAs
    fa_mma_kernel<<<grid, NT, SMEM_BYTES>>>(q, k, v, causal, out);
}

// round 7
// speedup vs baseline: 2.4414x; 2.4414x over previous
#include <cuda_runtime.h>
#include <cuda_fp16.h>
#include <math.h>
#include <stdint.h>

// FlashAttention fwd, causal, fp32 I/O, fp16 mma.sync (m16n8k16), sm_103.
// B=1, S=4096, H=16, D=64. Layout [s,h,d]: d contiguous, s stride 1024.
//
// Pre-pass kernel converts once: qh = half(q*scale), kh = half(k),
// vth = half(V^T per head) [h][d][s]. Main kernel: CTA = (head, 128 q rows),
// 4 warps x 32 rows, BN=64 kv tiles double-buffered via cp.async (half tiles,
// no in-loop cvt / transpose). All smem fragment accesses conflict-free
// (pitch 72 halves = 36 b32 ≡ 4 mod 32 -> bank = 4g+tg).

constexpr int S_LEN = 4096;
constexpr int H     = 16;
constexpr int Dh    = 64;
constexpr int BM    = 128;
constexpr int BN    = 64;
constexpr int NT    = 128;
constexpr int PH    = 72;        // smem pitch in halves

// smem offsets in halves
constexpr int KH_OFF  = 0;                    // 2 x 64x72
constexpr int VTH_OFF = 2 * BN * PH;          // 2 x 64x72
constexpr int PSH_OFF = 4 * BN * PH;          // 128x72 (Q staging / P)
constexpr int SMEM_H  = PSH_OFF + BM * PH;
constexpr int SMEM_BYTES = SMEM_H * 2;        // 55296 B -> 2 CTAs/SM

// one-time converted operands
__device__ __half qh_g[S_LEN * H * Dh];       // [s][h][d], pre-scaled
__device__ __half kh_g[S_LEN * H * Dh];       // [s][h][d]
__device__ __half vth_g[H * Dh * S_LEN];      // [h][d][s]  (V transposed)

__device__ __forceinline__ float ex2(float x) {
    float y;
    asm("ex2.approx.f32 %0, %1;" : "=f"(y) : "f"(x));
    return y;
}
__device__ __forceinline__ void mma16(float* d, const uint32_t* a, const uint32_t* b) {
    asm volatile(
        "mma.sync.aligned.m16n8k16.row.col.f32.f16.f16.f32 "
        "{%0,%1,%2,%3}, {%4,%5,%6,%7}, {%8,%9}, {%0,%1,%2,%3};"
        : "+f"(d[0]), "+f"(d[1]), "+f"(d[2]), "+f"(d[3])
        : "r"(a[0]), "r"(a[1]), "r"(a[2]), "r"(a[3]), "r"(b[0]), "r"(b[1]));
}
__device__ __forceinline__ void cpa16(uint32_t dst, const void* src) {
    asm volatile("cp.async.cg.shared.global [%0], [%1], 16;"
                 :: "r"(dst), "l"(src) : "memory");
}

// ---------------- pre-pass: fp32 -> fp16 (+scale Q, transpose V) ----------
__global__ void __launch_bounds__(NT)
cvt_kernel(const float* __restrict__ q, const float* __restrict__ k,
           const float* __restrict__ v)
{
    __shared__ __half vt_s[Dh][72];           // transposed V tile staging
    const int h  = blockIdx.x;
    const int s0 = blockIdx.y * 64;
    const int t  = threadIdx.x;
    const float c = 0.125f * 1.44269504088896340736f;   // D^-0.5 * log2(e)

    #pragma unroll
    for (int i = 0; i < 8; i++) {
        int idx = t + i * NT;                 // 0..1023
        int row = idx >> 4, c4 = idx & 15;    // 64 rows x 16 float4-chunks
        size_t g = (size_t)(s0 + row) * (H * Dh) + (size_t)h * Dh + c4 * 4;
        float4 fq = *(const float4*)(q + g);
        float4 fk = *(const float4*)(k + g);
        float4 fv = *(const float4*)(v + g);
        ((__half2*)(qh_g + g))[0] = __floats2half2_rn(fq.x * c, fq.y * c);
        ((__half2*)(qh_g + g))[1] = __floats2half2_rn(fq.z * c, fq.w * c);
        ((__half2*)(kh_g + g))[0] = __floats2half2_rn(fk.x, fk.y);
        ((__half2*)(kh_g + g))[1] = __floats2half2_rn(fk.z, fk.w);
        vt_s[c4 * 4 + 0][row] = __float2half_rn(fv.x);
        vt_s[c4 * 4 + 1][row] = __float2half_rn(fv.y);
        vt_s[c4 * 4 + 2][row] = __float2half_rn(fv.z);
        vt_s[c4 * 4 + 3][row] = __float2half_rn(fv.w);
    }
    __syncthreads();
    #pragma unroll
    for (int i = 0; i < 16; i++) {
        int idx = t + i * NT;                 // 0..2047 half2 chunks
        int d = idx >> 5, c2 = idx & 31;
        __half2 val = __halves2half2(vt_s[d][2 * c2], vt_s[d][2 * c2 + 1]);
        *(__half2*)(vth_g + ((size_t)h * Dh + d) * S_LEN + s0 + c2 * 2) = val;
    }
}

// copy one 64x64 K tile + Vt tile (half) -> smem; 4+4 16B chunks per thread
__device__ __forceinline__ void issue_tile(uint32_t kdst, uint32_t vdst,
                                           const __half* ksrc_h, int k0, int h,
                                           int t) {
    #pragma unroll
    for (int i = 0; i < 4; i++) {
        int idx = t + i * NT;                 // 0..511
        int row = idx >> 3, c = idx & 7;      // 64 rows x 8 16B-chunks
        cpa16(kdst + (uint32_t)(row * PH + c * 8) * 2,
              ksrc_h + (size_t)(k0 + row) * (H * Dh) + (size_t)h * Dh + c * 8);
        cpa16(vdst + (uint32_t)(row * PH + c * 8) * 2,
              vth_g + ((size_t)h * Dh + row) * S_LEN + k0 + c * 8);
    }
    asm volatile("cp.async.commit_group;" ::: "memory");
}

__global__ void __launch_bounds__(NT, 2)
fa_mma_kernel(const int* __restrict__ causal_p, float* __restrict__ out)
{
    extern __shared__ __half smh[];
    uint32_t smb;
    asm("{ .reg .u64 t; cvta.to.shared.u64 t, %1; cvt.u32.u64 %0, t; }"
        : "=r"(smb) : "l"(smh));
    __half* Psh = smh + PSH_OFF;

    const int t    = threadIdx.x;
    const int lane = t & 31;
    const int g    = lane >> 2;
    const int tg   = lane & 3;
    const int h    = blockIdx.x;
    const int qb   = (int)gridDim.y - 1 - (int)blockIdx.y;  // heavy tiles first
    const int causal = *causal_p;
    const int wb   = (t >> 5) * 32;       // warp's 32-row base in CTA tile
    const int q0   = qb * BM;
    const int ktiles = causal ? 2 * (qb + 1) : (S_LEN / BN);

    // ---- stage Q (group 0) and kv tile 0 (group 1)
    #pragma unroll
    for (int i = 0; i < 8; i++) {
        int idx = t + i * NT;                 // 0..1023
        int row = idx >> 3, c = idx & 7;
        cpa16(smb + (uint32_t)(PSH_OFF + row * PH + c * 8) * 2,
              qh_g + (size_t)(q0 + row) * (H * Dh) + (size_t)h * Dh + c * 8);
    }
    asm volatile("cp.async.commit_group;" ::: "memory");
    issue_tile(smb + KH_OFF * 2, smb + VTH_OFF * 2, kh_g, 0, h, t);

    asm volatile("cp.async.wait_group 1;" ::: "memory");   // Q ready
    __syncthreads();

    // ---- lift Q fragments (m16n8k16 A layout), rows warp-private
    uint32_t qa[2][4][4];                     // [mtile][ktile][frag]
    #pragma unroll
    for (int mt = 0; mt < 2; mt++) {
        int r0 = wb + mt * 16 + g;
        #pragma unroll
        for (int kt = 0; kt < 4; kt++) {
            const __half* p0 = Psh + r0 * PH + kt * 16 + 2 * tg;
            const __half* p1 = Psh + (r0 + 8) * PH + kt * 16 + 2 * tg;
            qa[mt][kt][0] = *(const uint32_t*)p0;
            qa[mt][kt][1] = *(const uint32_t*)p1;
            qa[mt][kt][2] = *(const uint32_t*)(p0 + 8);
            qa[mt][kt][3] = *(const uint32_t*)(p1 + 8);
        }
    }

    float o[2][8][4];
    #pragma unroll
    for (int mt = 0; mt < 2; mt++)
        #pragma unroll
        for (int nt = 0; nt < 8; nt++)
            #pragma unroll
            for (int e = 0; e < 4; e++) o[mt][nt][e] = 0.0f;
    float mrow[4] = {-INFINITY, -INFINITY, -INFINITY, -INFINITY};
    float lrow[4] = {0.0f, 0.0f, 0.0f, 0.0f};

    for (int kb = 0; kb < ktiles; kb++) {
        const int k0 = kb * BN;
        const int cur = kb & 1;
        const __half* Kh = smh + KH_OFF + cur * (BN * PH);
        const __half* Vh = smh + VTH_OFF + cur * (BN * PH);

        __syncthreads();   // prev iter's reads of buffer cur^1 / Psh done
        if (kb + 1 < ktiles)
            issue_tile(smb + (KH_OFF + (cur ^ 1) * BN * PH) * 2,
                       smb + (VTH_OFF + (cur ^ 1) * BN * PH) * 2,
                       kh_g, k0 + BN, h, t);
        else
            asm volatile("cp.async.commit_group;" ::: "memory");
        asm volatile("cp.async.wait_group 1;" ::: "memory");
        __syncthreads();   // tile kb visible CTA-wide

        // ---- MMA1: S[32 x 64] = Q @ K^T (4 k-steps of 16)
        float s[2][8][4];
        #pragma unroll
        for (int mt = 0; mt < 2; mt++)
            #pragma unroll
            for (int nt = 0; nt < 8; nt++)
                #pragma unroll
                for (int e = 0; e < 4; e++) s[mt][nt][e] = 0.0f;
        #pragma unroll
        for (int kt = 0; kt < 4; kt++) {
            #pragma unroll
            for (int nt = 0; nt < 8; nt++) {
                const __half* kp = Kh + (nt * 8 + g) * PH + kt * 16 + 2 * tg;
                uint32_t b[2];
                b[0] = *(const uint32_t*)kp;
                b[1] = *(const uint32_t*)(kp + 8);
                mma16(s[0][nt], qa[0][kt], b);
                mma16(s[1][nt], qa[1][kt], b);
            }
        }

        // ---- causal mask (diagonal tiles only)
        if (causal && kb >= 2 * qb) {
            #pragma unroll
            for (int mt = 0; mt < 2; mt++) {
                int r0 = q0 + wb + mt * 16 + g;
                #pragma unroll
                for (int nt = 0; nt < 8; nt++) {
                    int col = k0 + nt * 8 + 2 * tg;
                    if (col     > r0)     s[mt][nt][0] = -INFINITY;
                    if (col + 1 > r0)     s[mt][nt][1] = -INFINITY;
                    if (col     > r0 + 8) s[mt][nt][2] = -INFINITY;
                    if (col + 1 > r0 + 8) s[mt][nt][3] = -INFINITY;
                }
            }
        }

        // ---- online softmax (4 rows/thread; quad owns a row)
        #pragma unroll
        for (int mt = 0; mt < 2; mt++) {
            #pragma unroll
            for (int hi = 0; hi < 2; hi++) {
                const int ri = mt * 2 + hi;
                float tm = -INFINITY;
                #pragma unroll
                for (int nt = 0; nt < 8; nt++)
                    tm = fmaxf(tm, fmaxf(s[mt][nt][hi * 2], s[mt][nt][hi * 2 + 1]));
                tm = fmaxf(tm, __shfl_xor_sync(0xffffffffu, tm, 1));
                tm = fmaxf(tm, __shfl_xor_sync(0xffffffffu, tm, 2));
                float nm   = fmaxf(mrow[ri], tm);
                float corr = ex2(mrow[ri] - nm);     // first tile: -inf -> 0
                mrow[ri] = nm;
                float ls = 0.0f;
                #pragma unroll
                for (int nt = 0; nt < 8; nt++) {
                    float e0 = ex2(s[mt][nt][hi * 2]     - nm);
                    float e1 = ex2(s[mt][nt][hi * 2 + 1] - nm);
                    s[mt][nt][hi * 2]     = e0;
                    s[mt][nt][hi * 2 + 1] = e1;
                    ls += e0 + e1;
                    o[mt][nt][hi * 2]     *= corr;
                    o[mt][nt][hi * 2 + 1] *= corr;
                }
                lrow[ri] = lrow[ri] * corr + ls;
            }
        }

        // ---- P (rn half2) -> Psh; rows warp-private
        #pragma unroll
        for (int mt = 0; mt < 2; mt++) {
            int r0 = wb + mt * 16 + g;
            #pragma unroll
            for (int nt = 0; nt < 8; nt++) {
                *(__half2*)(Psh + r0 * PH + nt * 8 + 2 * tg) =
                    __floats2half2_rn(s[mt][nt][0], s[mt][nt][1]);
                *(__half2*)(Psh + (r0 + 8) * PH + nt * 8 + 2 * tg) =
                    __floats2half2_rn(s[mt][nt][2], s[mt][nt][3]);
            }
        }
        __syncwarp();

        // ---- MMA2: O += P[32x64] @ V[64x64]  (4 k-steps of 16)
        #pragma unroll
        for (int kt = 0; kt < 4; kt++) {
            uint32_t pa[2][4];
            #pragma unroll
            for (int mt = 0; mt < 2; mt++) {
                int r0 = wb + mt * 16 + g;
                const __half* p0 = Psh + r0 * PH + kt * 16 + 2 * tg;
                const __half* p1 = Psh + (r0 + 8) * PH + kt * 16 + 2 * tg;
                pa[mt][0] = *(const uint32_t*)p0;
                pa[mt][1] = *(const uint32_t*)p1;
                pa[mt][2] = *(const uint32_t*)(p0 + 8);
                pa[mt][3] = *(const uint32_t*)(p1 + 8);
            }
            #pragma unroll
            for (int nt = 0; nt < 8; nt++) {
                const __half* vp = Vh + (nt * 8 + g) * PH + kt * 16 + 2 * tg;
                uint32_t b[2];
                b[0] = *(const uint32_t*)vp;
                b[1] = *(const uint32_t*)(vp + 8);
                mma16(o[0][nt], pa[0], b);
                mma16(o[1][nt], pa[1], b);
            }
        }
    }

    // ---- finalize: row-sum across quad, normalize, store
    #pragma unroll
    for (int ri = 0; ri < 4; ri++) {
        lrow[ri] += __shfl_xor_sync(0xffffffffu, lrow[ri], 1);
        lrow[ri] += __shfl_xor_sync(0xffffffffu, lrow[ri], 2);
    }
    #pragma unroll
    for (int mt = 0; mt < 2; mt++) {
        #pragma unroll
        for (int hi = 0; hi < 2; hi++) {
            const int ri = mt * 2 + hi;
            const float inv = 1.0f / lrow[ri];
            const int rg = q0 + wb + mt * 16 + g + hi * 8;
            float* op = out + (size_t)rg * (H * Dh) + (size_t)h * Dh;
            #pragma unroll
            for (int nt = 0; nt < 8; nt++) {
                float2 f2;
                f2.x = o[mt][nt][hi * 2]     * inv;
                f2.y = o[mt][nt][hi * 2 + 1] * inv;
                *(float2*)(op + nt * 8 + 2 * tg) = f2;
            }
        }
    }
}

extern "C" void kernel_launch(void* const* d_in, const int* in_sizes, int n_in,
                              void* d_out, int out_size)
{
    const float* q = (const float*)d_in[0];
    const float* k = (const float*)d_in[1];
    const float* v = (const float*)d_in[2];
    const int* causal = (const int*)d_in[3];
    float* out = (float*)d_out;

    dim3 cgrid(H, S_LEN / 64);   // (16, 64)
    cvt_kernel<<<cgrid, NT>>>(q, k, v);

    cudaFuncSetAttribute(fa_mma_kernel,
                         cudaFuncAttributeMaxDynamicSharedMemorySize, SMEM_BYTES);
    dim3 grid(H, S_LEN / BM);    // (16, 32)
    fa_mma_kernel<<<grid, NT, SMEM_BYTES>>>(causal, out);
}